// round 14
// baseline (speedup 1.0000x reference)
#include <cuda_runtime.h>

#define Bz 8
#define Cc 512
#define Nn 2048
#define Dd 128
#define INV_SCALE 0.08838834764831845f   // 1/sqrt(128)

typedef unsigned long long ull;
typedef unsigned int u32;

// ------------------------- scratch (__device__ globals) --------------------
__device__ float g_qk [(size_t)Bz * Dd * Nn];   // [b][d][n]  8 MB
__device__ float g_v  [(size_t)Bz * Dd * Nn];   // [b][d][n]  8 MB
__device__ float g_vT [(size_t)Bz * Nn * Dd];   // [b][n][d] = v*linv  8 MB
__device__ float g_wT [2 * Cc * Dd];            // W transposed [which][c][d]
__device__ float g_P  [(size_t)Bz * Nn * Nn];   // exp(e) unnormalized, 128 MB
__device__ float g_lsum[Bz * Nn];
__device__ float g_linv[Bz * Nn];

// ------------------------- helpers -----------------------------------------
__device__ __forceinline__ u32 smem_u32(const void* p) {
    u32 a;
    asm("{ .reg .u64 t; cvta.to.shared.u64 t, %1; cvt.u32.u64 %0, t; }"
        : "=r"(a) : "l"(p));
    return a;
}
__device__ __forceinline__ void cp16(u32 dst, const void* src) {
    asm volatile("cp.async.ca.shared.global [%0], [%1], 16;"
                 :: "r"(dst), "l"(src));
}
#define CP_COMMIT() asm volatile("cp.async.commit_group;" ::: "memory")
#define CP_WAIT(n)  asm volatile("cp.async.wait_group %0;" :: "n"(n) : "memory")

__device__ __forceinline__ void fma2(ull& d, ull a, ull b) {
    asm("fma.rn.f32x2 %0, %1, %2, %0;" : "+l"(d) : "l"(a), "l"(b));
}
__device__ __forceinline__ ull pk2(float x) {
    ull r; asm("mov.b64 %0, {%1, %1};" : "=l"(r) : "f"(x)); return r;
}
__device__ __forceinline__ float2 upk(ull v) {
    float2 f; asm("mov.b64 {%0, %1}, %2;" : "=f"(f.x), "=f"(f.y) : "l"(v)); return f;
}

// 8x8 thread tile (256 thr -> 128x128 CTA tile). Ap/Bp point at one k-row.
#define MMA8x8(Ap, Bp)                                                         \
    {                                                                          \
        float4 a0 = *(const float4*)&(Ap)[ty8];                                \
        float4 a1 = *(const float4*)&(Ap)[ty8 + 4];                            \
        ulonglong2 b01 = *(const ulonglong2*)&(Bp)[tx8];                       \
        ulonglong2 b23 = *(const ulonglong2*)&(Bp)[tx8 + 4];                   \
        float a[8] = {a0.x, a0.y, a0.z, a0.w, a1.x, a1.y, a1.z, a1.w};         \
        _Pragma("unroll")                                                      \
        for (int r = 0; r < 8; ++r) {                                          \
            ull ad = pk2(a[r]);                                                \
            fma2(acc[r][0], ad, b01.x); fma2(acc[r][1], ad, b01.y);            \
            fma2(acc[r][2], ad, b23.x); fma2(acc[r][3], ad, b23.y);            \
        }                                                                      \
    }

// 4x8 thread tile (256 thr -> 128x64 CTA tile)
#define MMA4x8(Ap, Bp)                                                         \
    {                                                                          \
        float4 a0 = *(const float4*)&(Ap)[ty4];                                \
        ulonglong2 b01 = *(const ulonglong2*)&(Bp)[tx8];                       \
        ulonglong2 b23 = *(const ulonglong2*)&(Bp)[tx8 + 4];                   \
        float a[4] = {a0.x, a0.y, a0.z, a0.w};                                 \
        _Pragma("unroll")                                                      \
        for (int r = 0; r < 4; ++r) {                                          \
            ull ad = pk2(a[r]);                                                \
            fma2(acc[r][0], ad, b01.x); fma2(acc[r][1], ad, b01.y);            \
            fma2(acc[r][2], ad, b23.x); fma2(acc[r][3], ad, b23.y);            \
        }                                                                      \
    }

// ---------------------------------------------------------------------------
// tiny helpers
// ---------------------------------------------------------------------------
__global__ void zero_kernel() {
    int i = blockIdx.x * 1024 + threadIdx.x;
    if (i < Bz * Nn) g_lsum[i] = 0.0f;
}
__global__ void inv_kernel() {
    int i = blockIdx.x * 1024 + threadIdx.x;
    if (i < Bz * Nn) g_linv[i] = 1.0f / g_lsum[i];
}
// transpose weights: g_wT[which][c][d] = W[d][c]
__global__ void k_wT(const float* __restrict__ wqk, const float* __restrict__ wv) {
    __shared__ float T[32][33];
    const int ct = blockIdx.x, dt = blockIdx.y, which = blockIdx.z;
    const float* W = which ? wv : wqk;
    float* WT = g_wT + which * Cc * Dd;
    const int tx = threadIdx.x, ty = threadIdx.y;
    for (int yy = ty; yy < 32; yy += 8)
        T[yy][tx] = W[(dt * 32 + yy) * Cc + ct * 32 + tx];
    __syncthreads();
    for (int yy = ty; yy < 32; yy += 8)
        WT[(ct * 32 + yy) * Dd + dt * 32 + tx] = T[tx][yy];
}
// vT[n][d] = v[d][n] * linv[n]
__global__ void k_vT() {
    __shared__ float T[32][33];
    const int nt = blockIdx.x, dt = blockIdx.y, b = blockIdx.z;
    const float* vb = g_v + (size_t)b * Dd * Nn;
    float* vTb = g_vT + (size_t)b * Nn * Dd;
    const float* linvb = g_linv + b * Nn;
    const int tx = threadIdx.x, ty = threadIdx.y;
    for (int yy = ty; yy < 32; yy += 8)
        T[yy][tx] = vb[(size_t)(dt * 32 + yy) * Nn + nt * 32 + tx];
    __syncthreads();
    for (int yy = ty; yy < 32; yy += 8)
        vTb[(size_t)(nt * 32 + yy) * Dd + dt * 32 + tx] =
            T[tx][yy] * linvb[nt * 32 + yy];
}

// ---------------------------------------------------------------------------
// Kernel 1: projections, cp.async double-buffered.
// 128(d) x 128(n) tile; A = WT [c][d] direct, B = x [c][n] direct.
// ---------------------------------------------------------------------------
__global__ __launch_bounds__(256, 2) void proj3(
    const float* __restrict__ x, const float* __restrict__ bv)
{
    extern __shared__ float sm[];
    float* bufA = sm;          // 2 x 32x128
    float* bufB = sm + 8192;   // 2 x 32x128
    const int n0 = blockIdx.x * 128, which = blockIdx.y, b = blockIdx.z;
    const int tid = threadIdx.x;
    const int tx8 = (tid & 15) * 8, ty8 = (tid >> 4) * 8;
    const float* WT = g_wT + which * Cc * Dd;
    const float* xb = x + (size_t)b * Cc * Nn;
    const u32 sA = smem_u32(bufA), sB = smem_u32(bufB);

    ull acc[8][4] = {};

#define PROJ_ISSUE(c0, buf)                                                    \
    {                                                                          \
        u32 dA = sA + (buf) * 16384, dB = sB + (buf) * 16384;                  \
        _Pragma("unroll")                                                      \
        for (int q = 0; q < 4; ++q) {                                          \
            int slot = tid + q * 256;                                          \
            int row = slot >> 5, col4 = (slot & 31) * 4;                       \
            cp16(dA + slot * 16, WT + ((c0) + row) * Dd + col4);               \
            cp16(dB + slot * 16, xb + (size_t)((c0) + row) * Nn + n0 + col4);  \
        }                                                                      \
        CP_COMMIT();                                                           \
    }

    PROJ_ISSUE(0, 0);
    for (int c = 0; c < 16; ++c) {
        if (c + 1 < 16) { PROJ_ISSUE((c + 1) * 32, (c + 1) & 1); CP_WAIT(1); }
        else            { CP_WAIT(0); }
        __syncthreads();
        const float* A = bufA + (c & 1) * 4096;
        const float* B = bufB + (c & 1) * 4096;
        #pragma unroll
        for (int kk = 0; kk < 32; ++kk) MMA8x8(A + kk * 128, B + kk * 128);
        __syncthreads();
    }

    float* dst = which ? g_v : g_qk;
    #pragma unroll
    for (int r = 0; r < 8; ++r) {
        int d = ty8 + r;
        float add = which ? bv[d] : 0.0f;
        float2 c0 = upk(acc[r][0]), c1 = upk(acc[r][1]);
        float2 c2 = upk(acc[r][2]), c3 = upk(acc[r][3]);
        size_t o = ((size_t)b * Dd + d) * Nn + n0 + tx8;
        *(float4*)&dst[o]     = make_float4(c0.x + add, c0.y + add, c1.x + add, c1.y + add);
        *(float4*)&dst[o + 4] = make_float4(c2.x + add, c2.y + add, c3.x + add, c3.y + add);
    }
}

// ---------------------------------------------------------------------------
// Kernel 2: symmetric stats. Only upper-triangular tile pairs (i<=j): 136/256.
// e-tile = qk[:,n-range]^T qk[:,m-range] (K=128); P written both orientations;
// row sums (and col sums for off-diagonal) atomically into g_lsum.
// ---------------------------------------------------------------------------
__global__ __launch_bounds__(256, 2) void stats4()
{
    extern __shared__ float sm[];
    float* bufA = sm;          // 2 x 32x128
    float* bufB = sm + 8192;
    __shared__ float lsumS[128], csumS[128];

    int idx = blockIdx.x;
    const int b = blockIdx.y;
    int i = 0;
    while (idx >= 16 - i) { idx -= 16 - i; ++i; }
    const int j = i + idx;
    const int n0 = i * 128, m0 = j * 128;
    const bool diag = (i == j);

    const int tid = threadIdx.x;
    const int tx8 = (tid & 15) * 8, ty8 = (tid >> 4) * 8;
    const float* qkb = g_qk + (size_t)b * Dd * Nn;
    float* Pb = g_P + (size_t)b * Nn * Nn;
    const u32 sA = smem_u32(bufA), sB = smem_u32(bufB);

    if (tid < 128) { lsumS[tid] = 0.0f; csumS[tid] = 0.0f; }

    ull acc[8][4] = {};

#define STATS_ISSUE(c0, buf)                                                   \
    {                                                                          \
        u32 dA = sA + (buf) * 16384, dB = sB + (buf) * 16384;                  \
        _Pragma("unroll")                                                      \
        for (int q = 0; q < 4; ++q) {                                          \
            int slot = tid + q * 256;                                          \
            int row = slot >> 5, col4 = (slot & 31) * 4;                       \
            cp16(dA + slot * 16, qkb + (size_t)((c0) + row) * Nn + n0 + col4); \
            cp16(dB + slot * 16, qkb + (size_t)((c0) + row) * Nn + m0 + col4); \
        }                                                                      \
        CP_COMMIT();                                                           \
    }

    STATS_ISSUE(0, 0);
    for (int c = 0; c < 4; ++c) {
        if (c + 1 < 4) { STATS_ISSUE((c + 1) * 32, (c + 1) & 1); CP_WAIT(1); }
        else           { CP_WAIT(0); }
        __syncthreads();
        const float* A = bufA + (c & 1) * 4096;
        const float* B = bufB + (c & 1) * 4096;
        #pragma unroll
        for (int kk = 0; kk < 32; ++kk) MMA8x8(A + kk * 128, B + kk * 128);
        __syncthreads();
    }

    // epilogue
    float p[8][8];
    #pragma unroll
    for (int r = 0; r < 8; ++r)
        #pragma unroll
        for (int c = 0; c < 4; ++c) {
            float2 e2 = upk(acc[r][c]);
            p[r][2 * c]     = __expf(e2.x * INV_SCALE);
            p[r][2 * c + 1] = __expf(e2.y * INV_SCALE);
        }

    #pragma unroll
    for (int r = 0; r < 8; ++r) {
        float rs = 0.0f;
        #pragma unroll
        for (int c = 0; c < 8; ++c) rs += p[r][c];
        atomicAdd(&lsumS[ty8 + r], rs);
        size_t rb = (size_t)(n0 + ty8 + r) * Nn + m0 + tx8;
        *(float4*)&Pb[rb]     = make_float4(p[r][0], p[r][1], p[r][2], p[r][3]);
        *(float4*)&Pb[rb + 4] = make_float4(p[r][4], p[r][5], p[r][6], p[r][7]);
    }
    if (!diag) {
        #pragma unroll
        for (int c = 0; c < 8; ++c) {
            float cs = p[0][c] + p[1][c] + p[2][c] + p[3][c]
                     + p[4][c] + p[5][c] + p[6][c] + p[7][c];
            atomicAdd(&csumS[tx8 + c], cs);
            size_t rb = (size_t)(m0 + tx8 + c) * Nn + n0 + ty8;
            *(float4*)&Pb[rb]     = make_float4(p[0][c], p[1][c], p[2][c], p[3][c]);
            *(float4*)&Pb[rb + 4] = make_float4(p[4][c], p[5][c], p[6][c], p[7][c]);
        }
    }
    __syncthreads();
    if (tid < 128) {
        atomicAdd(&g_lsum[b * Nn + n0 + tid], lsumS[tid]);
        if (!diag) atomicAdd(&g_lsum[b * Nn + m0 + tid], csumS[tid]);
    }
}

// ---------------------------------------------------------------------------
// Kernel 3: out[d][m] = sum_n vT[n][d] * P[n][m].  K = 2048, 64 chunks of 32,
// cp.async double-buffered. CTA tile 128(d) x 64(m), thread tile 4x8.
// ---------------------------------------------------------------------------
__global__ __launch_bounds__(256, 2) void out4(float* __restrict__ out)
{
    extern __shared__ float sm[];
    float* bufA = sm;          // 2 x 32x128 (vT chunk)
    float* bufB = sm + 8192;   // 2 x 32x64  (P chunk)
    const int m0 = blockIdx.x * 64, b = blockIdx.y;
    const int tid = threadIdx.x;
    const int tx8 = (tid & 7) * 8, ty4 = (tid >> 3) * 4;
    const float* vTb = g_vT + (size_t)b * Nn * Dd;
    const float* Pb  = g_P  + (size_t)b * Nn * Nn;
    const u32 sA = smem_u32(bufA), sB = smem_u32(bufB);

    ull acc[4][4] = {};

#define OUT_ISSUE(nc, buf)                                                     \
    {                                                                          \
        u32 dA = sA + (buf) * 16384, dB = sB + (buf) * 8192;                   \
        _Pragma("unroll")                                                      \
        for (int q = 0; q < 4; ++q) {                                          \
            int slot = tid + q * 256;                                          \
            int row = slot >> 5, col4 = (slot & 31) * 4;                       \
            cp16(dA + slot * 16, vTb + (size_t)((nc) + row) * Dd + col4);      \
        }                                                                      \
        _Pragma("unroll")                                                      \
        for (int q = 0; q < 2; ++q) {                                          \
            int slot = tid + q * 256;                                          \
            int row = slot >> 4, col4 = (slot & 15) * 4;                       \
            cp16(dB + slot * 16, Pb + (size_t)((nc) + row) * Nn + m0 + col4);  \
        }                                                                      \
        CP_COMMIT();                                                           \
    }

    OUT_ISSUE(0, 0);
    for (int c = 0; c < 64; ++c) {
        if (c + 1 < 64) { OUT_ISSUE((c + 1) * 32, (c + 1) & 1); CP_WAIT(1); }
        else            { CP_WAIT(0); }
        __syncthreads();
        const float* A = bufA + (c & 1) * 4096;
        const float* B = bufB + (c & 1) * 2048;
        #pragma unroll
        for (int kk = 0; kk < 32; ++kk) MMA4x8(A + kk * 128, B + kk * 64);
        __syncthreads();
    }

    #pragma unroll
    for (int r = 0; r < 4; ++r) {
        int d = ty4 + r;
        float2 c0 = upk(acc[r][0]), c1 = upk(acc[r][1]);
        float2 c2 = upk(acc[r][2]), c3 = upk(acc[r][3]);
        size_t o = ((size_t)b * Dd + d) * Nn + m0 + tx8;
        *(float4*)&out[o]     = make_float4(c0.x, c0.y, c1.x, c1.y);
        *(float4*)&out[o + 4] = make_float4(c2.x, c2.y, c3.x, c3.y);
    }
}

// ---------------------------------------------------------------------------
extern "C" void kernel_launch(void* const* d_in, const int* in_sizes, int n_in,
                              void* d_out, int out_size)
{
    const float* x   = (const float*)d_in[0];   // [8, 512, 2048]
    const float* wqk = (const float*)d_in[1];   // [128, 512]
    const float* wv  = (const float*)d_in[2];   // [128, 512]
    const float* bv  = (const float*)d_in[3];   // [128]
    float* out = (float*)d_out;                 // [8, 128, 2048]

    cudaFuncSetAttribute(proj3,  cudaFuncAttributeMaxDynamicSharedMemorySize, 65536);
    cudaFuncSetAttribute(stats4, cudaFuncAttributeMaxDynamicSharedMemorySize, 65536);
    cudaFuncSetAttribute(out4,   cudaFuncAttributeMaxDynamicSharedMemorySize, 49152);

    k_wT        <<<dim3(Cc / 32, Dd / 32, 2), dim3(32, 8)>>>(wqk, wv);
    zero_kernel <<<16, 1024>>>();
    proj3       <<<dim3(Nn / 128, 2, Bz), 256, 65536>>>(x, bv);
    stats4      <<<dim3(136, Bz), 256, 65536>>>();
    inv_kernel  <<<16, 1024>>>();
    k_vT        <<<dim3(Nn / 32, Dd / 32, Bz), dim3(32, 8)>>>();
    out4        <<<dim3(Nn / 64, Bz), 256, 49152>>>(out);
}

// round 15
// speedup vs baseline: 1.2631x; 1.2631x over previous
#include <cuda_runtime.h>

#define Bz 8
#define Cc 512
#define Nn 2048
#define Dd 128
#define INV_SCALE 0.08838834764831845f   // 1/sqrt(128)

typedef unsigned long long ull;
typedef unsigned int u32;

// ------------------------- scratch (__device__ globals) --------------------
__device__ float g_qk [(size_t)Bz * Dd * Nn];   // [b][d][n]  8 MB
__device__ float g_v  [(size_t)Bz * Dd * Nn];   // [b][d][n]  8 MB
__device__ float g_vT [(size_t)Bz * Nn * Dd];   // [b][n][d] = v*linv  8 MB
__device__ float g_wT [2 * Cc * Dd];            // W transposed [which][c][d]
__device__ float g_P  [(size_t)Bz * Nn * Nn];   // exp(e) unnormalized, 128 MB
__device__ float g_lsum[Bz * Nn];
__device__ float g_linv[Bz * Nn];

// ------------------------- helpers -----------------------------------------
__device__ __forceinline__ u32 smem_u32(const void* p) {
    u32 a;
    asm("{ .reg .u64 t; cvta.to.shared.u64 t, %1; cvt.u32.u64 %0, t; }"
        : "=r"(a) : "l"(p));
    return a;
}
__device__ __forceinline__ void cp16(u32 dst, const float* src) {
    asm volatile("cp.async.ca.shared.global [%0], [%1], 16;"
                 :: "r"(dst), "l"(src));
}
#define CP_COMMIT() asm volatile("cp.async.commit_group;" ::: "memory")
#define CP_WAIT(n)  asm volatile("cp.async.wait_group %0;" :: "n"(n) : "memory")

__device__ __forceinline__ void fma2(ull& d, ull a, ull b) {
    asm("fma.rn.f32x2 %0, %1, %2, %0;" : "+l"(d) : "l"(a), "l"(b));
}
__device__ __forceinline__ ull pk2(float x) {
    ull r; asm("mov.b64 %0, {%1, %1};" : "=l"(r) : "f"(x)); return r;
}
__device__ __forceinline__ float2 upk(ull v) {
    float2 f; asm("mov.b64 {%0, %1}, %2;" : "=f"(f.x), "=f"(f.y) : "l"(v)); return f;
}

// 8x8 thread tile (256 thr -> 128x128 CTA tile). Ap/Bp point at one k-row.
#define MMA8x8(Ap, Bp)                                                         \
    {                                                                          \
        float4 a0 = *(const float4*)&(Ap)[ty8];                                \
        float4 a1 = *(const float4*)&(Ap)[ty8 + 4];                            \
        ulonglong2 b01 = *(const ulonglong2*)&(Bp)[tx8];                       \
        ulonglong2 b23 = *(const ulonglong2*)&(Bp)[tx8 + 4];                   \
        float a[8] = {a0.x, a0.y, a0.z, a0.w, a1.x, a1.y, a1.z, a1.w};         \
        _Pragma("unroll")                                                      \
        for (int r = 0; r < 8; ++r) {                                          \
            ull ad = pk2(a[r]);                                                \
            fma2(acc[r][0], ad, b01.x); fma2(acc[r][1], ad, b01.y);            \
            fma2(acc[r][2], ad, b23.x); fma2(acc[r][3], ad, b23.y);            \
        }                                                                      \
    }

// ---- 3-stage pipelined 128x128 GEMM engine ---------------------------------
// smem: bufA = sm[0 .. 3*4096), bufB = sm[12288 .. 12288+3*4096)  (96 KB)
// One __syncthreads per chunk: wait(1) -> sync -> issue(c+2) -> compute(c).
// The sync separates compute(c-1) from issue(c+2) (same stage mod 3).
#define GISSUE(Abase, strideA, Bbase, strideB, c0, stg)                        \
    {                                                                          \
        u32 dA = sA + (stg) * 16384, dB = sB + (stg) * 16384;                  \
        _Pragma("unroll")                                                      \
        for (int q = 0; q < 4; ++q) {                                          \
            int slot = tid + q * 256;                                          \
            int row = slot >> 5, col4 = (slot & 31) * 4;                       \
            cp16(dA + slot * 16, (Abase) + (size_t)((c0) + row) * (strideA) + col4); \
            cp16(dB + slot * 16, (Bbase) + (size_t)((c0) + row) * (strideB) + col4); \
        }                                                                      \
        CP_COMMIT();                                                           \
    }

#define GEMM_LOOP(NC, Abase, strideA, Bbase, strideB)                          \
    GISSUE(Abase, strideA, Bbase, strideB, 0, 0);                              \
    GISSUE(Abase, strideA, Bbase, strideB, 32, 1);                             \
    for (int c = 0; c < (NC); ++c) {                                           \
        if (c + 1 < (NC)) { CP_WAIT(1); } else { CP_WAIT(0); }                 \
        __syncthreads();                                                       \
        if (c + 2 < (NC))                                                      \
            GISSUE(Abase, strideA, Bbase, strideB, (c + 2) * 32, (c + 2) % 3); \
        const float* A_ = bufA + (c % 3) * 4096;                               \
        const float* B_ = bufB + (c % 3) * 4096;                               \
        _Pragma("unroll")                                                      \
        for (int kk = 0; kk < 32; ++kk) MMA8x8(A_ + kk * 128, B_ + kk * 128);  \
    }

#define GEMM_SMEM 98304

// ---------------------------------------------------------------------------
// tiny helpers
// ---------------------------------------------------------------------------
__global__ void zero_kernel() {
    int i = blockIdx.x * 1024 + threadIdx.x;
    if (i < Bz * Nn) g_lsum[i] = 0.0f;
}
__global__ void inv_kernel() {
    int i = blockIdx.x * 1024 + threadIdx.x;
    if (i < Bz * Nn) g_linv[i] = 1.0f / g_lsum[i];
}
__global__ void k_wT(const float* __restrict__ wqk, const float* __restrict__ wv) {
    __shared__ float T[32][33];
    const int ct = blockIdx.x, dt = blockIdx.y, which = blockIdx.z;
    const float* W = which ? wv : wqk;
    float* WT = g_wT + which * Cc * Dd;
    const int tx = threadIdx.x, ty = threadIdx.y;
    for (int yy = ty; yy < 32; yy += 8)
        T[yy][tx] = W[(dt * 32 + yy) * Cc + ct * 32 + tx];
    __syncthreads();
    for (int yy = ty; yy < 32; yy += 8)
        WT[(ct * 32 + yy) * Dd + dt * 32 + tx] = T[tx][yy];
}
__global__ void k_vT() {
    __shared__ float T[32][33];
    const int nt = blockIdx.x, dt = blockIdx.y, b = blockIdx.z;
    const float* vb = g_v + (size_t)b * Dd * Nn;
    float* vTb = g_vT + (size_t)b * Nn * Dd;
    const float* linvb = g_linv + b * Nn;
    const int tx = threadIdx.x, ty = threadIdx.y;
    for (int yy = ty; yy < 32; yy += 8)
        T[yy][tx] = vb[(size_t)(dt * 32 + yy) * Nn + nt * 32 + tx];
    __syncthreads();
    for (int yy = ty; yy < 32; yy += 8)
        vTb[(size_t)(nt * 32 + yy) * Dd + dt * 32 + tx] =
            T[tx][yy] * linvb[nt * 32 + yy];
}

// ---------------------------------------------------------------------------
// Kernel 1: projections. A = WT [c][d], B = x [c][n]. K = 512 (16 chunks).
// ---------------------------------------------------------------------------
__global__ __launch_bounds__(256, 2) void proj4(
    const float* __restrict__ x, const float* __restrict__ bv)
{
    extern __shared__ float sm[];
    float* bufA = sm;
    float* bufB = sm + 12288;
    const int n0 = blockIdx.x * 128, which = blockIdx.y, b = blockIdx.z;
    const int tid = threadIdx.x;
    const int tx8 = (tid & 15) * 8, ty8 = (tid >> 4) * 8;
    const float* WT = g_wT + which * Cc * Dd;
    const float* xb = x + (size_t)b * Cc * Nn + n0;
    const u32 sA = smem_u32(bufA), sB = smem_u32(bufB);

    ull acc[8][4] = {};
    GEMM_LOOP(16, WT, Dd, xb, Nn);

    float* dst = which ? g_v : g_qk;
    #pragma unroll
    for (int r = 0; r < 8; ++r) {
        int d = ty8 + r;
        float add = which ? bv[d] : 0.0f;
        float2 c0 = upk(acc[r][0]), c1 = upk(acc[r][1]);
        float2 c2 = upk(acc[r][2]), c3 = upk(acc[r][3]);
        size_t o = ((size_t)b * Dd + d) * Nn + n0 + tx8;
        *(float4*)&dst[o]     = make_float4(c0.x + add, c0.y + add, c1.x + add, c1.y + add);
        *(float4*)&dst[o + 4] = make_float4(c2.x + add, c2.y + add, c3.x + add, c3.y + add);
    }
}

// ---------------------------------------------------------------------------
// Kernel 2: symmetric stats, upper-triangular tile pairs (136/256). K = 128.
// P written in both orientations; row/col sums -> g_lsum (atomics).
// ---------------------------------------------------------------------------
__global__ __launch_bounds__(256, 2) void stats5()
{
    extern __shared__ float sm[];
    float* bufA = sm;
    float* bufB = sm + 12288;
    __shared__ float lsumS[128], csumS[128];

    int idx = blockIdx.x;
    const int b = blockIdx.y;
    int i = 0;
    while (idx >= 16 - i) { idx -= 16 - i; ++i; }
    const int j = i + idx;
    const int n0 = i * 128, m0 = j * 128;
    const bool diag = (i == j);

    const int tid = threadIdx.x;
    const int tx8 = (tid & 15) * 8, ty8 = (tid >> 4) * 8;
    const float* qkb = g_qk + (size_t)b * Dd * Nn;
    const float* An = qkb + n0;
    const float* Bm = qkb + m0;
    float* Pb = g_P + (size_t)b * Nn * Nn;
    const u32 sA = smem_u32(bufA), sB = smem_u32(bufB);

    if (tid < 128) { lsumS[tid] = 0.0f; csumS[tid] = 0.0f; }

    ull acc[8][4] = {};
    GEMM_LOOP(4, An, Nn, Bm, Nn);

    // epilogue: exp, dual-orientation store, row/col sums
    float p[8][8];
    #pragma unroll
    for (int r = 0; r < 8; ++r)
        #pragma unroll
        for (int c = 0; c < 4; ++c) {
            float2 e2 = upk(acc[r][c]);
            p[r][2 * c]     = __expf(e2.x * INV_SCALE);
            p[r][2 * c + 1] = __expf(e2.y * INV_SCALE);
        }

    #pragma unroll
    for (int r = 0; r < 8; ++r) {
        float rs = 0.0f;
        #pragma unroll
        for (int c = 0; c < 8; ++c) rs += p[r][c];
        atomicAdd(&lsumS[ty8 + r], rs);
        size_t rb = (size_t)(n0 + ty8 + r) * Nn + m0 + tx8;
        *(float4*)&Pb[rb]     = make_float4(p[r][0], p[r][1], p[r][2], p[r][3]);
        *(float4*)&Pb[rb + 4] = make_float4(p[r][4], p[r][5], p[r][6], p[r][7]);
    }
    if (!diag) {
        #pragma unroll
        for (int c = 0; c < 8; ++c) {
            float cs = p[0][c] + p[1][c] + p[2][c] + p[3][c]
                     + p[4][c] + p[5][c] + p[6][c] + p[7][c];
            atomicAdd(&csumS[tx8 + c], cs);
            size_t rb = (size_t)(m0 + tx8 + c) * Nn + n0 + ty8;
            *(float4*)&Pb[rb]     = make_float4(p[0][c], p[1][c], p[2][c], p[3][c]);
            *(float4*)&Pb[rb + 4] = make_float4(p[4][c], p[5][c], p[6][c], p[7][c]);
        }
    }
    __syncthreads();
    if (tid < 128) {
        atomicAdd(&g_lsum[b * Nn + n0 + tid], lsumS[tid]);
        if (!diag) atomicAdd(&g_lsum[b * Nn + m0 + tid], csumS[tid]);
    }
}

// ---------------------------------------------------------------------------
// Kernel 3: out[d][m] = sum_n vT[n][d] * P[n][m].  128x128 tile, K = 2048
// (64 chunks). grid 128 -> 1 CTA/SM, full register file for pipelining.
// ---------------------------------------------------------------------------
__global__ __launch_bounds__(256, 1) void out5(float* __restrict__ out)
{
    extern __shared__ float sm[];
    float* bufA = sm;
    float* bufB = sm + 12288;
    const int m0 = blockIdx.x * 128, b = blockIdx.y;
    const int tid = threadIdx.x;
    const int tx8 = (tid & 15) * 8, ty8 = (tid >> 4) * 8;
    const float* vTb = g_vT + (size_t)b * Nn * Dd;
    const float* Pm  = g_P  + (size_t)b * Nn * Nn + m0;
    const u32 sA = smem_u32(bufA), sB = smem_u32(bufB);

    ull acc[8][4] = {};
    GEMM_LOOP(64, vTb, Dd, Pm, Nn);

    #pragma unroll
    for (int r = 0; r < 8; ++r) {
        int d = ty8 + r;
        float2 c0 = upk(acc[r][0]), c1 = upk(acc[r][1]);
        float2 c2 = upk(acc[r][2]), c3 = upk(acc[r][3]);
        size_t o = ((size_t)b * Dd + d) * Nn + m0 + tx8;
        *(float4*)&out[o]     = make_float4(c0.x, c0.y, c1.x, c1.y);
        *(float4*)&out[o + 4] = make_float4(c2.x, c2.y, c3.x, c3.y);
    }
}

// ---------------------------------------------------------------------------
extern "C" void kernel_launch(void* const* d_in, const int* in_sizes, int n_in,
                              void* d_out, int out_size)
{
    const float* x   = (const float*)d_in[0];   // [8, 512, 2048]
    const float* wqk = (const float*)d_in[1];   // [128, 512]
    const float* wv  = (const float*)d_in[2];   // [128, 512]
    const float* bv  = (const float*)d_in[3];   // [128]
    float* out = (float*)d_out;                 // [8, 128, 2048]

    cudaFuncSetAttribute(proj4,  cudaFuncAttributeMaxDynamicSharedMemorySize, GEMM_SMEM);
    cudaFuncSetAttribute(stats5, cudaFuncAttributeMaxDynamicSharedMemorySize, GEMM_SMEM);
    cudaFuncSetAttribute(out5,   cudaFuncAttributeMaxDynamicSharedMemorySize, GEMM_SMEM);

    k_wT        <<<dim3(Cc / 32, Dd / 32, 2), dim3(32, 8)>>>(wqk, wv);
    zero_kernel <<<16, 1024>>>();
    proj4       <<<dim3(Nn / 128, 2, Bz), 256, GEMM_SMEM>>>(x, bv);
    stats5      <<<dim3(136, Bz), 256, GEMM_SMEM>>>();
    inv_kernel  <<<16, 1024>>>();
    k_vT        <<<dim3(Nn / 32, Dd / 32, Bz), dim3(32, 8)>>>();
    out5        <<<dim3(Nn / 128, Bz), 256, GEMM_SMEM>>>(out);
}